// round 13
// baseline (speedup 1.0000x reference)
#include <cuda_runtime.h>
#include <cuda_fp16.h>
#include <math.h>
#include <stdint.h>

#define Bb 4
#define Ss 4096
#define Ee 512
#define DKk 64
#define ROWS (Bb*Ss)
#define BQ 128
#define BK 128
#define NKT (Ss/BK)     // 32

// Scratch (device globals)
__device__ __align__(16) __half g_Wt[3*DKk*Ee];     // [w][n][k] fp16
__device__ __align__(16) __half g_Q[ROWS*DKk];      // fp16, prescaled 0.125*log2(e), unmasked
__device__ __align__(16) __half g_K[ROWS*DKk];      // fp16, unmasked
__device__ __align__(16) __half g_Vt[Bb*DKk*Ss];    // [b][d][s] fp16, unmasked
__device__ __align__(16) __half g_maskh[ROWS];      // 1.0 / 0.0
__device__ int g_lencnt[Bb];

#define ONESH2 0x3C003C00u   // f16x2 {1.0, 1.0}

// ---------------- helpers ----------------
__device__ __forceinline__ uint32_t smem_u32(const void* p) {
    uint32_t a;
    asm("{ .reg .u64 t; cvta.to.shared.u64 t, %1; cvt.u32.u64 %0, t; }" : "=r"(a) : "l"(p));
    return a;
}
#define SWZ(o) ((o) ^ (((o) >> 3) & 0x70))
#define CP16(dst,src)   asm volatile("cp.async.cg.shared.global [%0], [%1], 16;" :: "r"(dst), "l"(src))
#define CP_COMMIT()     asm volatile("cp.async.commit_group;" ::: "memory")
#define CP_WAIT0()      asm volatile("cp.async.wait_group 0;" ::: "memory")

__device__ __forceinline__ void ldsm_x4(uint32_t* r, uint32_t addr) {
    asm volatile("ldmatrix.sync.aligned.m8n8.x4.shared.b16 {%0,%1,%2,%3}, [%4];"
        : "=r"(r[0]), "=r"(r[1]), "=r"(r[2]), "=r"(r[3]) : "r"(addr));
}
__device__ __forceinline__ void mma16816(float* c, const uint32_t* a, uint32_t b0, uint32_t b1) {
    asm volatile("mma.sync.aligned.m16n8k16.row.col.f32.f16.f16.f32 "
        "{%0,%1,%2,%3}, {%4,%5,%6,%7}, {%8,%9}, {%0,%1,%2,%3};"
        : "+f"(c[0]), "+f"(c[1]), "+f"(c[2]), "+f"(c[3])
        : "r"(a[0]), "r"(a[1]), "r"(a[2]), "r"(a[3]), "r"(b0), "r"(b1));
}
__device__ __forceinline__ void mma16816h(uint32_t* c, const uint32_t* a, uint32_t b0, uint32_t b1) {
    asm volatile("mma.sync.aligned.m16n8k16.row.col.f16.f16.f16.f16 "
        "{%0,%1}, {%2,%3,%4,%5}, {%6,%7}, {%0,%1};"
        : "+r"(c[0]), "+r"(c[1])
        : "r"(a[0]), "r"(a[1]), "r"(a[2]), "r"(a[3]), "r"(b0), "r"(b1));
}
__device__ __forceinline__ uint32_t pack2h(float e0, float e1) {
    __half2 hh = __floats2half2_rn(e0, e1);
    return *reinterpret_cast<uint32_t*>(&hh);
}
__device__ __forceinline__ uint32_t ex2h2(uint32_t a) {
    uint32_t d;
    asm("ex2.approx.f16x2 %0, %1;" : "=r"(d) : "r"(a));
    return d;
}
__device__ __forceinline__ float ex2f(float a) {
    float d;
    asm("ex2.approx.f32 %0, %1;" : "=f"(d) : "f"(a));
    return d;
}

// ---------------------------------------------------------------------------
// 1) W transpose -> fp16  [w][n=64][k=512], coalesced via smem tile
// ---------------------------------------------------------------------------
__global__ __launch_bounds__(256) void wsplit_kernel(
    const float* __restrict__ Wq, const float* __restrict__ Wk,
    const float* __restrict__ Wv)
{
    if (blockIdx.x == 0 && blockIdx.y == 0 && threadIdx.x < Bb)
        g_lencnt[threadIdx.x] = 0;
    __shared__ float s[64 * 65];
    int w = blockIdx.x;
    const float* W = (w == 0) ? Wq : ((w == 1) ? Wk : Wv);
    __half* dst = g_Wt + (size_t)w * DKk * Ee;
    int k0 = blockIdx.y * 64;
    int r = threadIdx.x >> 6;
    int c = threadIdx.x & 63;
#pragma unroll
    for (int i = 0; i < 16; i++) {
        int kk = i * 4 + r;
        s[kk * 65 + c] = W[(size_t)(k0 + kk) * DKk + c];   // coalesced read
    }
    __syncthreads();
#pragma unroll
    for (int i = 0; i < 16; i++) {
        int n = i * 4 + r;
        dst[(size_t)n * Ee + k0 + c] = __float2half_rn(s[c * 65 + n]);   // coalesced write
    }
}

// ---------------------------------------------------------------------------
// 2) Fused projections, resident-A (unchanged from R12):
//    y=0: x -> Q (mask + lencnt), y=1: ctx -> K then Vt (resident A replay)
// ---------------------------------------------------------------------------
#define PA_CH(c)  ((c) * 16384)
#define PJ_W(s)   (131072 + (s) * 8192)
#define PJ_VT     147456
#define PJ_SMEM   (1024 + 147456 + 32768)   // 181248

__device__ __forceinline__ void pj_stage_w(uint32_t wb, const __half* wsrc, int it, int tid)
{
    int kb = it * 64;
#pragma unroll
    for (int i = 0; i < 2; i++) {
        int cid = tid + 256 * i;
        int r = cid >> 3, c = cid & 7;
        uint32_t off = SWZ((uint32_t)(r * 128 + c * 16));
        CP16(wb + off, wsrc + (size_t)r * Ee + kb + c * 8);
    }
}

__global__ __launch_bounds__(256, 1) void proj_kernel(
    const float* __restrict__ x, const float* __restrict__ ctx)
{
    extern __shared__ char smraw[];
    uint32_t raw32 = smem_u32(smraw);
    uint32_t sm32 = (raw32 + 1023) & ~1023u;
    char* sm = smraw + (sm32 - raw32);

    int tid  = threadIdx.x;
    int lane = tid & 31;
    int wid  = tid >> 5;
    int g    = lane >> 2;
    int qc   = lane & 3;
    int r0   = wid * 16;
    int brow = lane & 7;
    int bcol = (lane >> 3) * 16;

    int which = blockIdx.y;
    int rb = blockIdx.x * 128;
    const float* A = which ? ctx : x;
    const __half* w1 = g_Wt + (size_t)(which ? 1 : 0) * DKk * Ee;
    const __half* wv = g_Wt + (size_t)2 * DKk * Ee;

    float4 a4[8];
#pragma unroll
    for (int i = 0; i < 8; i++) {
        int cid = tid + 256 * i;
        int r = cid >> 4, c4 = (cid & 15) * 4;
        a4[i] = *(const float4*)(A + (size_t)(rb + r) * Ee + c4);
    }
    pj_stage_w(sm32 + PJ_W(0), w1, 0, tid);
    CP_COMMIT();

    unsigned nzbits = 0;
    float c[8][4];
#pragma unroll
    for (int n = 0; n < 8; n++)
#pragma unroll
        for (int j = 0; j < 4; j++) c[n][j] = 0.f;

    int arow = r0 + (lane & 7) + ((lane >> 3) & 1) * 8;
    int acolb = (lane >> 4) * 16;

    for (int it = 0; it < 8; it++) {
        CP_WAIT0();
        __syncthreads();

#pragma unroll
        for (int i = 0; i < 8; i++) {
            int cid = tid + 256 * i;
            int r = cid >> 4, c4 = (cid & 15) * 4;
            float4 v = a4[i];
            if (which == 0) {
                bool nz = (v.x != 0.f) || (v.y != 0.f) || (v.z != 0.f) || (v.w != 0.f);
                nzbits |= nz ? (1u << i) : 0u;
            }
            uint2 H; H.x = pack2h(v.x, v.y); H.y = pack2h(v.z, v.w);
            *(uint2*)(sm + PA_CH(it) + SWZ((uint32_t)(r * 128 + c4 * 2))) = H;
        }
        if (it < 7) {
            int kb = (it + 1) * 64;
#pragma unroll
            for (int i = 0; i < 8; i++) {
                int cid = tid + 256 * i;
                int r = cid >> 4, c4 = (cid & 15) * 4;
                a4[i] = *(const float4*)(A + (size_t)(rb + r) * Ee + kb + c4);
            }
            pj_stage_w(sm32 + PJ_W((it + 1) & 1), w1, it + 1, tid);
            CP_COMMIT();
        } else if (which == 1) {
            pj_stage_w(sm32 + PJ_W(0), wv, 0, tid);
            CP_COMMIT();
        }
        __syncthreads();

        uint32_t wb = sm32 + PJ_W(it & 1);
        uint32_t ab = sm32 + PA_CH(it);
        uint32_t ah[16];
#pragma unroll
        for (int kf = 0; kf < 4; kf++)
            ldsm_x4(ah + kf * 4, ab + SWZ((uint32_t)(arow * 128 + kf * 32 + acolb)));
#pragma unroll
        for (int n = 0; n < 8; n++) {
            uint32_t bh[8];
            uint32_t rowb = (uint32_t)((n * 8 + brow) * 128);
            ldsm_x4(bh,     wb + SWZ(rowb + bcol));
            ldsm_x4(bh + 4, wb + SWZ(rowb + 64 + bcol));
#pragma unroll
            for (int kf = 0; kf < 4; kf++) mma16816(c[n], ah + kf*4, bh[2*kf], bh[2*kf+1]);
        }
    }

    int rowA = rb + r0 + g;
    int rowB = rowA + 8;

    if (which == 0) {
#pragma unroll
        for (int off = 1; off < 16; off <<= 1)
            nzbits |= __shfl_xor_sync(0xffffffffu, nzbits, off);
        if ((lane & 15) == 0) {
            int rg = tid >> 4;
#pragma unroll
            for (int i = 0; i < 8; i++)
                g_maskh[rb + rg + 16 * i] = __float2half(((nzbits >> i) & 1) ? 1.f : 0.f);
            atomicAdd(&g_lencnt[rb >> 12], __popc(nzbits & 0xFFu));
        }
        float scale = 0.125f * 1.44269504f;
#pragma unroll
        for (int dn = 0; dn < 8; dn++) {
            int col = dn * 8 + qc * 2;
            *(uint32_t*)&g_Q[(size_t)rowA * DKk + col] = pack2h(c[dn][0] * scale, c[dn][1] * scale);
            *(uint32_t*)&g_Q[(size_t)rowB * DKk + col] = pack2h(c[dn][2] * scale, c[dn][3] * scale);
        }
        return;
    }

#pragma unroll
    for (int dn = 0; dn < 8; dn++) {
        int col = dn * 8 + qc * 2;
        *(uint32_t*)&g_K[(size_t)rowA * DKk + col] = pack2h(c[dn][0], c[dn][1]);
        *(uint32_t*)&g_K[(size_t)rowB * DKk + col] = pack2h(c[dn][2], c[dn][3]);
    }

    // ---- pass 2: V = resident A @ Wv ----
#pragma unroll
    for (int n = 0; n < 8; n++)
#pragma unroll
        for (int j = 0; j < 4; j++) c[n][j] = 0.f;

    for (int it = 0; it < 8; it++) {
        CP_WAIT0();
        __syncthreads();
        if (it < 7) {
            pj_stage_w(sm32 + PJ_W((it + 1) & 1), wv, it + 1, tid);
            CP_COMMIT();
        }
        uint32_t wb = sm32 + PJ_W(it & 1);
        uint32_t ab = sm32 + PA_CH(it);
        uint32_t ah[16];
#pragma unroll
        for (int kf = 0; kf < 4; kf++)
            ldsm_x4(ah + kf * 4, ab + SWZ((uint32_t)(arow * 128 + kf * 32 + acolb)));
#pragma unroll
        for (int n = 0; n < 8; n++) {
            uint32_t bh[8];
            uint32_t rowb = (uint32_t)((n * 8 + brow) * 128);
            ldsm_x4(bh,     wb + SWZ(rowb + bcol));
            ldsm_x4(bh + 4, wb + SWZ(rowb + 64 + bcol));
#pragma unroll
            for (int kf = 0; kf < 4; kf++) mma16816(c[n], ah + kf*4, bh[2*kf], bh[2*kf+1]);
        }
    }

    float* sVt = (float*)(sm + PJ_VT);
    __syncthreads();
#pragma unroll
    for (int dn = 0; dn < 8; dn++) {
        int col = dn * 8 + qc * 2;
        int rA = r0 + g, rB = rA + 8;
        sVt[(col    ) * 128 + rA] = c[dn][0];
        sVt[(col + 1) * 128 + rA] = c[dn][1];
        sVt[(col    ) * 128 + rB] = c[dn][2];
        sVt[(col + 1) * 128 + rB] = c[dn][3];
    }
    __syncthreads();
    int bb = rb >> 12;
    int sgb = rb & (Ss - 1);
#pragma unroll
    for (int i = 0; i < 4; i++) {
        int gi = tid + 256 * i;
        int d = gi >> 4, s0 = (gi & 15) * 8;
        uint32_t h[4];
#pragma unroll
        for (int j = 0; j < 4; j++)
            h[j] = pack2h(sVt[d * 128 + s0 + 2*j], sVt[d * 128 + s0 + 2*j + 1]);
        size_t dst = ((size_t)(bb * DKk + d)) * Ss + sgb + s0;
        *(uint4*)&g_Vt[dst] = make_uint4(h[0], h[1], h[2], h[3]);
    }
}

// ---------------------------------------------------------------------------
// 3) Flash attention: BQ=128, 256 threads (8 warps), 32 q-rows/warp,
//    keys split 2-way. B-fragments reused across both m-sets.
// ---------------------------------------------------------------------------
#define SM_Q     0
#define SM_STG0  16384
#define STG_SZ   33792
#define ST_K     0
#define ST_V     16384
#define ST_M     32768
#define SMEM_BYTES (1024 + SM_STG0 + 2*STG_SZ)   // 84992

__device__ __forceinline__ void stage_kv(uint32_t sm32, int stage, int b, int kb, int tid) {
    uint32_t sb = sm32 + SM_STG0 + stage * STG_SZ;
#pragma unroll
    for (int i = 0; i < 4; i++) {
        int cid = tid + 256 * i;
        int r = cid >> 3, c = cid & 7;
        uint32_t off = SWZ((uint32_t)(r * 128 + c * 16));
        CP16(sb + ST_K + off, g_K + (size_t)(b * Ss + kb + r) * DKk + c * 8);
    }
#pragma unroll
    for (int i = 0; i < 4; i++) {
        int cid = tid + 256 * i;
        int sub = cid >> 9, rem = cid & 511;
        int d = rem >> 3, c = rem & 7;
        uint32_t off = (uint32_t)(sub * 8192) + SWZ((uint32_t)(d * 128 + c * 16));
        CP16(sb + ST_V + off, g_Vt + (size_t)(b * DKk + d) * Ss + kb + sub * 64 + c * 8);
    }
    if (tid < 16)
        CP16(sb + ST_M + tid * 16, g_maskh + (size_t)b * Ss + kb + tid * 8);
}

__global__ __launch_bounds__(256, 1) void attn_kernel(float* __restrict__ out) {
    extern __shared__ char smraw[];
    uint32_t raw32 = smem_u32(smraw);
    uint32_t sm32 = (raw32 + 1023) & ~1023u;
    char* sm = smraw + (sm32 - raw32);

    int tid  = threadIdx.x;
    int wid  = tid >> 5;
    int lane = tid & 31;
    int half = wid >> 2;          // key half
    int wq   = wid & 3;
    int g    = lane >> 2;
    int qc   = lane & 3;
    int r0   = wq * 32;           // 32 q-rows per warp

    int b  = blockIdx.x >> 5;
    int qb = (blockIdx.x & 31) * BQ;
    int len = (__half2float(g_maskh[(size_t)b * Ss]) != 0.f) ? g_lencnt[b] : 0;
    bool fast = (len == Ss);

    // stage Q (128 rows = 1024 chunks) + first KV tile
#pragma unroll
    for (int i = 0; i < 4; i++) {
        int cid = tid + 256 * i;
        int rr = cid >> 3, c = cid & 7;
        uint32_t off = SWZ((uint32_t)(rr * 128 + c * 16));
        CP16(sm32 + SM_Q + off, g_Q + (size_t)(b * Ss + qb + rr) * DKk + c * 8);
    }
    stage_kv(sm32, 0, b, 0, tid);
    CP_COMMIT();
    CP_WAIT0();
    __syncthreads();

    uint32_t qh[2][16];
#pragma unroll
    for (int mset = 0; mset < 2; mset++) {
        int row = r0 + mset * 16 + (lane & 7) + ((lane >> 3) & 1) * 8;
        int colb = (lane >> 4) * 16;
#pragma unroll
        for (int kf = 0; kf < 4; kf++)
            ldsm_x4(qh[mset] + kf * 4, sm32 + SM_Q + SWZ((uint32_t)(row * 128 + kf * 32 + colb)));
    }

    float o[2][8][4];
#pragma unroll
    for (int m = 0; m < 2; m++)
#pragma unroll
        for (int dn = 0; dn < 8; dn++)
#pragma unroll
            for (int j = 0; j < 4; j++) o[m][dn][j] = 0.f;
    float crs[2][4] = {{0.f,0.f,0.f,0.f},{0.f,0.f,0.f,0.f}};
    float rscA[2] = {0.f, 0.f}, rscB[2] = {0.f, 0.f};

    int brow = lane & 7;
    int bcol = (lane >> 3) * 16;

    for (int kt = 0; kt < NKT; kt++) {
        int kb = kt * BK;
        uint32_t stg = sm32 + SM_STG0 + (kt & 1) * STG_SZ;
        char* stgc = sm + SM_STG0 + (kt & 1) * STG_SZ;

        if (kt + 1 < NKT) { stage_kv(sm32, (kt + 1) & 1, b, kb + BK, tid); CP_COMMIT(); }

        uint32_t kbase = stg + ST_K + half * 8192;
        uint32_t vbase = stg + ST_V + half * 8192;
        const __half* sMask = (const __half*)(stgc + ST_M) + half * 64;
        int colsbase = kb + half * 64;

#pragma unroll
        for (int kp = 0; kp < 2; kp++) {
            uint32_t phi[2][8];
#pragma unroll
            for (int nn = 0; nn < 4; nn++) {
                int n = kp * 4 + nn;
                uint32_t bh[8];
                uint32_t rowb = (uint32_t)((n * 8 + brow) * 128);
                ldsm_x4(bh,     kbase + SWZ(rowb + bcol));
                ldsm_x4(bh + 4, kbase + SWZ(rowb + 64 + bcol));
                int kfl = nn >> 1, rofs = (nn & 1) * 2;
#pragma unroll
                for (int mset = 0; mset < 2; mset++) {
                    uint32_t s2[2]; s2[0] = 0u; s2[1] = 0u;
#pragma unroll
                    for (int kf = 0; kf < 4; kf++)
                        mma16816h(s2, qh[mset] + kf*4, bh[2*kf], bh[2*kf+1]);
                    if (fast) {
                        phi[mset][kfl * 4 + rofs]     = ex2h2(s2[0]);
                        phi[mset][kfl * 4 + rofs + 1] = ex2h2(s2[1]);
                    } else {
                        float2 sf0 = __half22float2(*(__half2*)&s2[0]);
                        float2 sf1 = __half22float2(*(__half2*)&s2[1]);
                        __half2 m2 = *(const __half2*)(sMask + n * 8 + qc * 2);
                        float2 mf = __half22float2(m2);
                        float e0 = ex2f(sf0.x) * mf.x;
                        float e1 = ex2f(sf0.y) * mf.y;
                        float e2 = ex2f(sf1.x) * mf.x;
                        float e3 = ex2f(sf1.y) * mf.y;
                        int col = colsbase + n * 8 + qc * 2;
                        bool v0 = col < len, v1 = col + 1 < len;
                        e0 = v0 ? e0 : 0.f;  e1 = v1 ? e1 : 0.f;
                        e2 = v0 ? e2 : 0.f;  e3 = v1 ? e3 : 0.f;
                        float a0 = v0 ? (1.f - mf.x) : 0.f;
                        float a1 = v1 ? (1.f - mf.y) : 0.f;
                        rscA[mset] += a0 + a1;
                        rscB[mset] += a0 + a1;
                        phi[mset][kfl * 4 + rofs]     = pack2h(e0, e1);
                        phi[mset][kfl * 4 + rofs + 1] = pack2h(e2, e3);
                    }
                }
            }

            // rs via ones-MMA
#pragma unroll
            for (int mset = 0; mset < 2; mset++) {
                mma16816(crs[mset], phi[mset],     ONESH2, ONESH2);
                mma16816(crs[mset], phi[mset] + 4, ONESH2, ONESH2);
            }

            // PV: load V frag once, reuse for both m-sets
#pragma unroll
            for (int dn = 0; dn < 8; dn++) {
                uint32_t vh[4];
                uint32_t rowb = (uint32_t)((dn * 8 + brow) * 128 + kp * 64);
                ldsm_x4(vh, vbase + SWZ(rowb + bcol));
#pragma unroll
                for (int mset = 0; mset < 2; mset++) {
                    mma16816(o[mset][dn], phi[mset],     vh[0], vh[1]);
                    mma16816(o[mset][dn], phi[mset] + 4, vh[2], vh[3]);
                }
            }
        }

        CP_WAIT0();
        __syncthreads();
    }

    // ---- epilogue ----
    float rsA[2], rsB[2];
#pragma unroll
    for (int mset = 0; mset < 2; mset++) {
        float a = rscA[mset], bq = rscB[mset];
        a += __shfl_xor_sync(0xffffffffu, a, 1);
        a += __shfl_xor_sync(0xffffffffu, a, 2);
        bq += __shfl_xor_sync(0xffffffffu, bq, 1);
        bq += __shfl_xor_sync(0xffffffffu, bq, 2);
        rsA[mset] = crs[mset][0] + a;
        rsB[mset] = crs[mset][2] + bq;
    }

    float* red   = (float*)(sm + SM_STG0);             // 128 x 66 fp32 = 33792B
    float* redrs = (float*)(sm + SM_STG0 + STG_SZ);    // 128 fp32

    if (half == 1) {
#pragma unroll
        for (int mset = 0; mset < 2; mset++) {
            int rA = r0 + mset * 16 + g, rB = rA + 8;
            if (qc == 0) { redrs[rA] = rsA[mset]; redrs[rB] = rsB[mset]; }
#pragma unroll
            for (int dn = 0; dn < 8; dn++) {
                int col = dn * 8 + qc * 2;
                *(float2*)&red[rA * 66 + col] = make_float2(o[mset][dn][0], o[mset][dn][1]);
                *(float2*)&red[rB * 66 + col] = make_float2(o[mset][dn][2], o[mset][dn][3]);
            }
        }
    }
    __syncthreads();
    if (half == 0) {
#pragma unroll
        for (int mset = 0; mset < 2; mset++) {
            int rA = r0 + mset * 16 + g, rB = rA + 8;
            float rs0 = rsA[mset] + redrs[rA];
            float rs1 = rsB[mset] + redrs[rB];
            int rowA = b * Ss + qb + rA;
            int rowB = b * Ss + qb + rB;
            float sc0 = __half2float(g_maskh[rowA]) / rs0;
            float sc1 = __half2float(g_maskh[rowB]) / rs1;
#pragma unroll
            for (int dn = 0; dn < 8; dn++) {
                int col = dn * 8 + qc * 2;
                float2 a = *(float2*)&red[rA * 66 + col];
                float2 bb2 = *(float2*)&red[rB * 66 + col];
                float2 vA; vA.x = (o[mset][dn][0] + a.x) * sc0;   vA.y = (o[mset][dn][1] + a.y) * sc0;
                float2 vB; vB.x = (o[mset][dn][2] + bb2.x) * sc1; vB.y = (o[mset][dn][3] + bb2.y) * sc1;
                *(float2*)(out + (size_t)rowA * DKk + col) = vA;
                *(float2*)(out + (size_t)rowB * DKk + col) = vB;
            }
        }
    }
}

// ---------------------------------------------------------------------------
extern "C" void kernel_launch(void* const* d_in, const int* in_sizes, int n_in,
                              void* d_out, int out_size) {
    const float* x   = (const float*)d_in[0];
    const float* ctx = (const float*)d_in[1];
    const float* Wq  = (const float*)d_in[2];
    const float* Wk  = (const float*)d_in[3];
    const float* Wv  = (const float*)d_in[4];
    float* out = (float*)d_out;

    cudaFuncSetAttribute(attn_kernel, cudaFuncAttributeMaxDynamicSharedMemorySize, SMEM_BYTES);
    cudaFuncSetAttribute(proj_kernel, cudaFuncAttributeMaxDynamicSharedMemorySize, PJ_SMEM);

    wsplit_kernel<<<dim3(3, 8), 256>>>(Wq, Wk, Wv);
    proj_kernel<<<dim3(ROWS / 128, 2), 256, PJ_SMEM>>>(x, ctx);
    attn_kernel<<<ROWS / BQ, 256, SMEM_BYTES>>>(out);
}

// round 14
// speedup vs baseline: 1.1491x; 1.1491x over previous
#include <cuda_runtime.h>
#include <cuda_fp16.h>
#include <math.h>
#include <stdint.h>

#define Bb 4
#define Ss 4096
#define Ee 512
#define DKk 64
#define ROWS (Bb*Ss)
#define BQ 64
#define BK 128
#define NKT (Ss/BK)     // 32

// Scratch (device globals)
__device__ __align__(16) __half g_Wt[3*DKk*Ee];     // [w][n][k] fp16
__device__ __align__(16) __half g_Q[ROWS*DKk];      // fp16, prescaled 0.125*log2(e), unmasked
__device__ __align__(16) __half g_K[ROWS*DKk];      // fp16, unmasked
__device__ __align__(16) __half g_Vt[Bb*DKk*Ss];    // [b][d][s] fp16, unmasked
__device__ __align__(16) __half g_maskh[ROWS];      // 1.0 / 0.0
__device__ int g_lencnt[Bb];

#define ONESH2 0x3C003C00u   // f16x2 {1.0, 1.0}

// ---------------- helpers ----------------
__device__ __forceinline__ uint32_t smem_u32(const void* p) {
    uint32_t a;
    asm("{ .reg .u64 t; cvta.to.shared.u64 t, %1; cvt.u32.u64 %0, t; }" : "=r"(a) : "l"(p));
    return a;
}
#define SWZ(o) ((o) ^ (((o) >> 3) & 0x70))
#define CP16(dst,src)   asm volatile("cp.async.cg.shared.global [%0], [%1], 16;" :: "r"(dst), "l"(src))
#define CP_COMMIT()     asm volatile("cp.async.commit_group;" ::: "memory")
#define CP_WAIT0()      asm volatile("cp.async.wait_group 0;" ::: "memory")

__device__ __forceinline__ void ldsm_x4(uint32_t* r, uint32_t addr) {
    asm volatile("ldmatrix.sync.aligned.m8n8.x4.shared.b16 {%0,%1,%2,%3}, [%4];"
        : "=r"(r[0]), "=r"(r[1]), "=r"(r[2]), "=r"(r[3]) : "r"(addr));
}
__device__ __forceinline__ void mma16816(float* c, const uint32_t* a, uint32_t b0, uint32_t b1) {
    asm volatile("mma.sync.aligned.m16n8k16.row.col.f32.f16.f16.f32 "
        "{%0,%1,%2,%3}, {%4,%5,%6,%7}, {%8,%9}, {%0,%1,%2,%3};"
        : "+f"(c[0]), "+f"(c[1]), "+f"(c[2]), "+f"(c[3])
        : "r"(a[0]), "r"(a[1]), "r"(a[2]), "r"(a[3]), "r"(b0), "r"(b1));
}
__device__ __forceinline__ void mma16816h(uint32_t* c, const uint32_t* a, uint32_t b0, uint32_t b1) {
    asm volatile("mma.sync.aligned.m16n8k16.row.col.f16.f16.f16.f16 "
        "{%0,%1}, {%2,%3,%4,%5}, {%6,%7}, {%0,%1};"
        : "+r"(c[0]), "+r"(c[1])
        : "r"(a[0]), "r"(a[1]), "r"(a[2]), "r"(a[3]), "r"(b0), "r"(b1));
}
__device__ __forceinline__ uint32_t pack2h(float e0, float e1) {
    __half2 hh = __floats2half2_rn(e0, e1);
    return *reinterpret_cast<uint32_t*>(&hh);
}
__device__ __forceinline__ uint32_t ex2h2(uint32_t a) {
    uint32_t d;
    asm("ex2.approx.f16x2 %0, %1;" : "=r"(d) : "r"(a));
    return d;
}
__device__ __forceinline__ float ex2f(float a) {
    float d;
    asm("ex2.approx.f32 %0, %1;" : "=f"(d) : "f"(a));
    return d;
}

// ---------------------------------------------------------------------------
// 1) W transpose -> fp16  [w][n=64][k=512], coalesced via smem tile
// ---------------------------------------------------------------------------
__global__ __launch_bounds__(256) void wsplit_kernel(
    const float* __restrict__ Wq, const float* __restrict__ Wk,
    const float* __restrict__ Wv)
{
    if (blockIdx.x == 0 && blockIdx.y == 0 && threadIdx.x < Bb)
        g_lencnt[threadIdx.x] = 0;
    __shared__ float s[64 * 65];
    int w = blockIdx.x;
    const float* W = (w == 0) ? Wq : ((w == 1) ? Wk : Wv);
    __half* dst = g_Wt + (size_t)w * DKk * Ee;
    int k0 = blockIdx.y * 64;
    int r = threadIdx.x >> 6;
    int c = threadIdx.x & 63;
#pragma unroll
    for (int i = 0; i < 16; i++) {
        int kk = i * 4 + r;
        s[kk * 65 + c] = W[(size_t)(k0 + kk) * DKk + c];   // coalesced read
    }
    __syncthreads();
#pragma unroll
    for (int i = 0; i < 16; i++) {
        int n = i * 4 + r;
        dst[(size_t)n * Ee + k0 + c] = __float2half_rn(s[c * 65 + n]);   // coalesced write
    }
}

// ---------------------------------------------------------------------------
// 2) Fused projections, resident-A:
//    y=0: x -> Q (mask + lencnt), y=1: ctx -> K then Vt (resident A replay)
// ---------------------------------------------------------------------------
#define PA_CH(c)  ((c) * 16384)
#define PJ_W(s)   (131072 + (s) * 8192)
#define PJ_VT     147456
#define PJ_SMEM   (1024 + 147456 + 32768)   // 181248

__device__ __forceinline__ void pj_stage_w(uint32_t wb, const __half* wsrc, int it, int tid)
{
    int kb = it * 64;
#pragma unroll
    for (int i = 0; i < 2; i++) {
        int cid = tid + 256 * i;
        int r = cid >> 3, c = cid & 7;
        uint32_t off = SWZ((uint32_t)(r * 128 + c * 16));
        CP16(wb + off, wsrc + (size_t)r * Ee + kb + c * 8);
    }
}

__global__ __launch_bounds__(256, 1) void proj_kernel(
    const float* __restrict__ x, const float* __restrict__ ctx)
{
    extern __shared__ char smraw[];
    uint32_t raw32 = smem_u32(smraw);
    uint32_t sm32 = (raw32 + 1023) & ~1023u;
    char* sm = smraw + (sm32 - raw32);

    int tid  = threadIdx.x;
    int lane = tid & 31;
    int wid  = tid >> 5;
    int g    = lane >> 2;
    int qc   = lane & 3;
    int r0   = wid * 16;
    int brow = lane & 7;
    int bcol = (lane >> 3) * 16;

    int which = blockIdx.y;
    int rb = blockIdx.x * 128;
    const float* A = which ? ctx : x;
    const __half* w1 = g_Wt + (size_t)(which ? 1 : 0) * DKk * Ee;
    const __half* wv = g_Wt + (size_t)2 * DKk * Ee;

    float4 a4[8];
#pragma unroll
    for (int i = 0; i < 8; i++) {
        int cid = tid + 256 * i;
        int r = cid >> 4, c4 = (cid & 15) * 4;
        a4[i] = *(const float4*)(A + (size_t)(rb + r) * Ee + c4);
    }
    pj_stage_w(sm32 + PJ_W(0), w1, 0, tid);
    CP_COMMIT();

    unsigned nzbits = 0;
    float c[8][4];
#pragma unroll
    for (int n = 0; n < 8; n++)
#pragma unroll
        for (int j = 0; j < 4; j++) c[n][j] = 0.f;

    int arow = r0 + (lane & 7) + ((lane >> 3) & 1) * 8;
    int acolb = (lane >> 4) * 16;

    for (int it = 0; it < 8; it++) {
        CP_WAIT0();
        __syncthreads();

#pragma unroll
        for (int i = 0; i < 8; i++) {
            int cid = tid + 256 * i;
            int r = cid >> 4, c4 = (cid & 15) * 4;
            float4 v = a4[i];
            if (which == 0) {
                bool nz = (v.x != 0.f) || (v.y != 0.f) || (v.z != 0.f) || (v.w != 0.f);
                nzbits |= nz ? (1u << i) : 0u;
            }
            uint2 H; H.x = pack2h(v.x, v.y); H.y = pack2h(v.z, v.w);
            *(uint2*)(sm + PA_CH(it) + SWZ((uint32_t)(r * 128 + c4 * 2))) = H;
        }
        if (it < 7) {
            int kb = (it + 1) * 64;
#pragma unroll
            for (int i = 0; i < 8; i++) {
                int cid = tid + 256 * i;
                int r = cid >> 4, c4 = (cid & 15) * 4;
                a4[i] = *(const float4*)(A + (size_t)(rb + r) * Ee + kb + c4);
            }
            pj_stage_w(sm32 + PJ_W((it + 1) & 1), w1, it + 1, tid);
            CP_COMMIT();
        } else if (which == 1) {
            pj_stage_w(sm32 + PJ_W(0), wv, 0, tid);
            CP_COMMIT();
        }
        __syncthreads();

        uint32_t wb = sm32 + PJ_W(it & 1);
        uint32_t ab = sm32 + PA_CH(it);
        uint32_t ah[16];
#pragma unroll
        for (int kf = 0; kf < 4; kf++)
            ldsm_x4(ah + kf * 4, ab + SWZ((uint32_t)(arow * 128 + kf * 32 + acolb)));
#pragma unroll
        for (int n = 0; n < 8; n++) {
            uint32_t bh[8];
            uint32_t rowb = (uint32_t)((n * 8 + brow) * 128);
            ldsm_x4(bh,     wb + SWZ(rowb + bcol));
            ldsm_x4(bh + 4, wb + SWZ(rowb + 64 + bcol));
#pragma unroll
            for (int kf = 0; kf < 4; kf++) mma16816(c[n], ah + kf*4, bh[2*kf], bh[2*kf+1]);
        }
    }

    int rowA = rb + r0 + g;
    int rowB = rowA + 8;

    if (which == 0) {
#pragma unroll
        for (int off = 1; off < 16; off <<= 1)
            nzbits |= __shfl_xor_sync(0xffffffffu, nzbits, off);
        if ((lane & 15) == 0) {
            int rg = tid >> 4;
#pragma unroll
            for (int i = 0; i < 8; i++)
                g_maskh[rb + rg + 16 * i] = __float2half(((nzbits >> i) & 1) ? 1.f : 0.f);
            atomicAdd(&g_lencnt[rb >> 12], __popc(nzbits & 0xFFu));
        }
        float scale = 0.125f * 1.44269504f;
#pragma unroll
        for (int dn = 0; dn < 8; dn++) {
            int col = dn * 8 + qc * 2;
            *(uint32_t*)&g_Q[(size_t)rowA * DKk + col] = pack2h(c[dn][0] * scale, c[dn][1] * scale);
            *(uint32_t*)&g_Q[(size_t)rowB * DKk + col] = pack2h(c[dn][2] * scale, c[dn][3] * scale);
        }
        return;
    }

#pragma unroll
    for (int dn = 0; dn < 8; dn++) {
        int col = dn * 8 + qc * 2;
        *(uint32_t*)&g_K[(size_t)rowA * DKk + col] = pack2h(c[dn][0], c[dn][1]);
        *(uint32_t*)&g_K[(size_t)rowB * DKk + col] = pack2h(c[dn][2], c[dn][3]);
    }

    // ---- pass 2: V = resident A @ Wv ----
#pragma unroll
    for (int n = 0; n < 8; n++)
#pragma unroll
        for (int j = 0; j < 4; j++) c[n][j] = 0.f;

    for (int it = 0; it < 8; it++) {
        CP_WAIT0();
        __syncthreads();
        if (it < 7) {
            pj_stage_w(sm32 + PJ_W((it + 1) & 1), wv, it + 1, tid);
            CP_COMMIT();
        }
        uint32_t wb = sm32 + PJ_W(it & 1);
        uint32_t ab = sm32 + PA_CH(it);
        uint32_t ah[16];
#pragma unroll
        for (int kf = 0; kf < 4; kf++)
            ldsm_x4(ah + kf * 4, ab + SWZ((uint32_t)(arow * 128 + kf * 32 + acolb)));
#pragma unroll
        for (int n = 0; n < 8; n++) {
            uint32_t bh[8];
            uint32_t rowb = (uint32_t)((n * 8 + brow) * 128);
            ldsm_x4(bh,     wb + SWZ(rowb + bcol));
            ldsm_x4(bh + 4, wb + SWZ(rowb + 64 + bcol));
#pragma unroll
            for (int kf = 0; kf < 4; kf++) mma16816(c[n], ah + kf*4, bh[2*kf], bh[2*kf+1]);
        }
    }

    float* sVt = (float*)(sm + PJ_VT);
    __syncthreads();
#pragma unroll
    for (int dn = 0; dn < 8; dn++) {
        int col = dn * 8 + qc * 2;
        int rA = r0 + g, rB = rA + 8;
        sVt[(col    ) * 128 + rA] = c[dn][0];
        sVt[(col + 1) * 128 + rA] = c[dn][1];
        sVt[(col    ) * 128 + rB] = c[dn][2];
        sVt[(col + 1) * 128 + rB] = c[dn][3];
    }
    __syncthreads();
    int bb = rb >> 12;
    int sgb = rb & (Ss - 1);
#pragma unroll
    for (int i = 0; i < 4; i++) {
        int gi = tid + 256 * i;
        int d = gi >> 4, s0 = (gi & 15) * 8;
        uint32_t h[4];
#pragma unroll
        for (int j = 0; j < 4; j++)
            h[j] = pack2h(sVt[d * 128 + s0 + 2*j], sVt[d * 128 + s0 + 2*j + 1]);
        size_t dst = ((size_t)(bb * DKk + d)) * Ss + sgb + s0;
        *(uint4*)&g_Vt[dst] = make_uint4(h[0], h[1], h[2], h[3]);
    }
}

// ---------------------------------------------------------------------------
// 3) Flash attention: BQ=64, 256 threads, keys split 2-way (proven R12 config)
// ---------------------------------------------------------------------------
#define SM_Q     0
#define SM_STG0  8192
#define STG_SZ   33792
#define ST_K     0
#define ST_V     16384
#define ST_M     32768
#define SMEM_BYTES (1024 + SM_STG0 + 2*STG_SZ)   // 76800

__device__ __forceinline__ void stage_kv(uint32_t sm32, int stage, int b, int kb, int tid) {
    uint32_t sb = sm32 + SM_STG0 + stage * STG_SZ;
#pragma unroll
    for (int i = 0; i < 4; i++) {
        int cid = tid + 256 * i;
        int r = cid >> 3, c = cid & 7;
        uint32_t off = SWZ((uint32_t)(r * 128 + c * 16));
        CP16(sb + ST_K + off, g_K + (size_t)(b * Ss + kb + r) * DKk + c * 8);
    }
#pragma unroll
    for (int i = 0; i < 4; i++) {
        int cid = tid + 256 * i;
        int sub = cid >> 9, rem = cid & 511;
        int d = rem >> 3, c = rem & 7;
        uint32_t off = (uint32_t)(sub * 8192) + SWZ((uint32_t)(d * 128 + c * 16));
        CP16(sb + ST_V + off, g_Vt + (size_t)(b * DKk + d) * Ss + kb + sub * 64 + c * 8);
    }
    if (tid < 16)
        CP16(sb + ST_M + tid * 16, g_maskh + (size_t)b * Ss + kb + tid * 8);
}

__global__ __launch_bounds__(256, 2) void attn_kernel(float* __restrict__ out) {
    extern __shared__ char smraw[];
    uint32_t raw32 = smem_u32(smraw);
    uint32_t sm32 = (raw32 + 1023) & ~1023u;
    char* sm = smraw + (sm32 - raw32);

    int tid  = threadIdx.x;
    int wid  = tid >> 5;
    int lane = tid & 31;
    int half = wid >> 2;
    int wq   = wid & 3;
    int g    = lane >> 2;
    int qc   = lane & 3;
    int r0   = wq * 16;

    int b  = blockIdx.x >> 6;
    int qb = (blockIdx.x & 63) * BQ;
    int len = (__half2float(g_maskh[(size_t)b * Ss]) != 0.f) ? g_lencnt[b] : 0;
    bool fast = (len == Ss);

#pragma unroll
    for (int i = 0; i < 2; i++) {
        int cid = tid + 256 * i;
        int rr = cid >> 3, c = cid & 7;
        uint32_t off = SWZ((uint32_t)(rr * 128 + c * 16));
        CP16(sm32 + SM_Q + off, g_Q + (size_t)(b * Ss + qb + rr) * DKk + c * 8);
    }
    stage_kv(sm32, 0, b, 0, tid);
    CP_COMMIT();
    CP_WAIT0();
    __syncthreads();

    uint32_t qh[16];
    {
        int row = r0 + (lane & 7) + ((lane >> 3) & 1) * 8;
        int colb = (lane >> 4) * 16;
#pragma unroll
        for (int kf = 0; kf < 4; kf++)
            ldsm_x4(qh + kf * 4, sm32 + SM_Q + SWZ((uint32_t)(row * 128 + kf * 32 + colb)));
    }

    float o[8][4];
#pragma unroll
    for (int dn = 0; dn < 8; dn++)
#pragma unroll
        for (int j = 0; j < 4; j++) o[dn][j] = 0.f;
    float crs[4] = {0.f, 0.f, 0.f, 0.f};
    float rsc0 = 0.f, rsc1 = 0.f;

    int brow = lane & 7;
    int bcol = (lane >> 3) * 16;

    for (int kt = 0; kt < NKT; kt++) {
        int kb = kt * BK;
        uint32_t stg = sm32 + SM_STG0 + (kt & 1) * STG_SZ;
        char* stgc = sm + SM_STG0 + (kt & 1) * STG_SZ;

        if (kt + 1 < NKT) { stage_kv(sm32, (kt + 1) & 1, b, kb + BK, tid); CP_COMMIT(); }

        uint32_t kbase = stg + ST_K + half * 8192;
        uint32_t vbase = stg + ST_V + half * 8192;
        const __half* sMask = (const __half*)(stgc + ST_M) + half * 64;
        int colsbase = kb + half * 64;

#pragma unroll
        for (int kp = 0; kp < 2; kp++) {
            uint32_t s2[4][2];
#pragma unroll
            for (int nn = 0; nn < 4; nn++) {
                int n = kp * 4 + nn;
                uint32_t bh[8];
                uint32_t rowb = (uint32_t)((n * 8 + brow) * 128);
                ldsm_x4(bh,     kbase + SWZ(rowb + bcol));
                ldsm_x4(bh + 4, kbase + SWZ(rowb + 64 + bcol));
                s2[nn][0] = 0u; s2[nn][1] = 0u;
#pragma unroll
                for (int kf = 0; kf < 4; kf++) mma16816h(s2[nn], qh + kf*4, bh[2*kf], bh[2*kf+1]);
            }

            uint32_t phi[8];
            if (fast) {
#pragma unroll
                for (int nn = 0; nn < 4; nn++) {
                    int kfl = nn >> 1, rofs = (nn & 1) * 2;
                    phi[kfl * 4 + rofs]     = ex2h2(s2[nn][0]);
                    phi[kfl * 4 + rofs + 1] = ex2h2(s2[nn][1]);
                }
            } else {
#pragma unroll
                for (int nn = 0; nn < 4; nn++) {
                    int n = kp * 4 + nn;
                    float2 sf0 = __half22float2(*(__half2*)&s2[nn][0]);
                    float2 sf1 = __half22float2(*(__half2*)&s2[nn][1]);
                    __half2 m2 = *(const __half2*)(sMask + n * 8 + qc * 2);
                    float2 mf = __half22float2(m2);
                    float e0 = ex2f(sf0.x) * mf.x;
                    float e1 = ex2f(sf0.y) * mf.y;
                    float e2 = ex2f(sf1.x) * mf.x;
                    float e3 = ex2f(sf1.y) * mf.y;
                    int col = colsbase + n * 8 + qc * 2;
                    bool v0 = col < len, v1 = col + 1 < len;
                    e0 = v0 ? e0 : 0.f;  e1 = v1 ? e1 : 0.f;
                    e2 = v0 ? e2 : 0.f;  e3 = v1 ? e3 : 0.f;
                    float a0 = v0 ? (1.f - mf.x) : 0.f;
                    float a1 = v1 ? (1.f - mf.y) : 0.f;
                    rsc0 += a0 + a1;
                    rsc1 += a0 + a1;
                    int kfl = nn >> 1, rofs = (nn & 1) * 2;
                    phi[kfl * 4 + rofs]     = pack2h(e0, e1);
                    phi[kfl * 4 + rofs + 1] = pack2h(e2, e3);
                }
            }

            mma16816(crs, phi,     ONESH2, ONESH2);
            mma16816(crs, phi + 4, ONESH2, ONESH2);

#pragma unroll
            for (int dn = 0; dn < 8; dn++) {
                uint32_t vh[4];
                uint32_t rowb = (uint32_t)((dn * 8 + brow) * 128 + kp * 64);
                ldsm_x4(vh, vbase + SWZ(rowb + bcol));
                mma16816(o[dn], phi,     vh[0], vh[1]);
                mma16816(o[dn], phi + 4, vh[2], vh[3]);
            }
        }

        CP_WAIT0();
        __syncthreads();
    }

    // ---- epilogue ----
    rsc0 += __shfl_xor_sync(0xffffffffu, rsc0, 1);
    rsc0 += __shfl_xor_sync(0xffffffffu, rsc0, 2);
    rsc1 += __shfl_xor_sync(0xffffffffu, rsc1, 1);
    rsc1 += __shfl_xor_sync(0xffffffffu, rsc1, 2);
    float rs0 = crs[0] + rsc0;
    float rs1 = crs[2] + rsc1;

    float* red   = (float*)(sm + SM_STG0);
    float* redrs = red + 64 * 66;

    if (half == 1) {
        int rA = r0 + g, rB = rA + 8;
        if (qc == 0) { redrs[rA] = rs0; redrs[rB] = rs1; }
#pragma unroll
        for (int dn = 0; dn < 8; dn++) {
            int col = dn * 8 + qc * 2;
            *(float2*)&red[rA * 66 + col] = make_float2(o[dn][0], o[dn][1]);
            *(float2*)&red[rB * 66 + col] = make_float2(o[dn][2], o[dn][3]);
        }
    }
    __syncthreads();
    if (half == 0) {
        int rA = r0 + g, rB = rA + 8;
        rs0 += redrs[rA];
        rs1 += redrs[rB];
        int rowA = b * Ss + qb + rA;
        int rowB = b * Ss + qb + rB;
        float sc0 = __half2float(g_maskh[rowA]) / rs0;
        float sc1 = __half2float(g_maskh[rowB]) / rs1;
#pragma unroll
        for (int dn = 0; dn < 8; dn++) {
            int col = dn * 8 + qc * 2;
            float2 a = *(float2*)&red[rA * 66 + col];
            float2 bb2 = *(float2*)&red[rB * 66 + col];
            float2 vA; vA.x = (o[dn][0] + a.x) * sc0;   vA.y = (o[dn][1] + a.y) * sc0;
            float2 vB; vB.x = (o[dn][2] + bb2.x) * sc1; vB.y = (o[dn][3] + bb2.y) * sc1;
            *(float2*)(out + (size_t)rowA * DKk + col) = vA;
            *(float2*)(out + (size_t)rowB * DKk + col) = vB;
        }
    }
}

// ---------------------------------------------------------------------------
extern "C" void kernel_launch(void* const* d_in, const int* in_sizes, int n_in,
                              void* d_out, int out_size) {
    const float* x   = (const float*)d_in[0];
    const float* ctx = (const float*)d_in[1];
    const float* Wq  = (const float*)d_in[2];
    const float* Wk  = (const float*)d_in[3];
    const float* Wv  = (const float*)d_in[4];
    float* out = (float*)d_out;

    cudaFuncSetAttribute(attn_kernel, cudaFuncAttributeMaxDynamicSharedMemorySize, SMEM_BYTES);
    cudaFuncSetAttribute(proj_kernel, cudaFuncAttributeMaxDynamicSharedMemorySize, PJ_SMEM);

    wsplit_kernel<<<dim3(3, 8), 256>>>(Wq, Wk, Wv);
    proj_kernel<<<dim3(ROWS / 128, 2), 256, PJ_SMEM>>>(x, ctx);
    attn_kernel<<<ROWS / BQ, 256, SMEM_BYTES>>>(out);
}